// round 7
// baseline (speedup 1.0000x reference)
#include <cuda_runtime.h>
#include <cuda_fp16.h>
#include <cstdint>

#define BB 2
#define SS 2048
#define DD 1024
#define HH 16
#define HD 64
#define GM (BB*SS)   // 4096
#define GN DD
#define GK DD

// ---------------------------------------------------------------------------
// Device-global scratch (fp16 hi/lo pairs)
// ---------------------------------------------------------------------------
__device__ __half g_xhi[GM*DD], g_xlo[GM*DD];
__device__ __half g_wThi[4*DD*DD], g_wTlo[4*DD*DD];   // W^T [N,K] hi/lo
__device__ __half g_qhi[GM*DD], g_qlo[GM*DD];          // [B,H,S,HD], pre-scaled 1/8
__device__ __half g_khi[GM*DD], g_klo[GM*DD];
__device__ __half g_vhi[GM*DD], g_vlo[GM*DD];
__device__ __half g_ohi[GM*DD], g_olo[GM*DD];          // [B*S, D] attn out

// ---------------------------------------------------------------------------
// Helpers
// ---------------------------------------------------------------------------
__device__ __forceinline__ uint32_t smem_u32(const void* p) {
    uint32_t a;
    asm("{ .reg .u64 t; cvta.to.shared.u64 t, %1; cvt.u32.u64 %0, t; }"
        : "=r"(a) : "l"(p));
    return a;
}

__device__ __forceinline__ uint32_t swz(uint32_t row, uint32_t cc) {
    return row * 128u + ((cc ^ (row & 7u)) << 4);
}

__device__ __forceinline__ void cp_async16(uint32_t s, const void* g) {
    asm volatile("cp.async.cg.shared.global [%0], [%1], 16;" :: "r"(s), "l"(g));
}
__device__ __forceinline__ void cp_async4(uint32_t s, const void* g) {
    asm volatile("cp.async.ca.shared.global [%0], [%1], 4;" :: "r"(s), "l"(g));
}
#define CP_COMMIT()  asm volatile("cp.async.commit_group;")
#define CP_WAIT1()   asm volatile("cp.async.wait_group 1;")
#define CP_WAIT0()   asm volatile("cp.async.wait_group 0;")

__device__ __forceinline__ void ldsm_x4(uint32_t* r, uint32_t a) {
    asm volatile("ldmatrix.sync.aligned.m8n8.x4.shared.b16 {%0,%1,%2,%3}, [%4];"
        : "=r"(r[0]), "=r"(r[1]), "=r"(r[2]), "=r"(r[3]) : "r"(a));
}
__device__ __forceinline__ void ldsm_x4_t(uint32_t* r, uint32_t a) {
    asm volatile("ldmatrix.sync.aligned.m8n8.x4.trans.shared.b16 {%0,%1,%2,%3}, [%4];"
        : "=r"(r[0]), "=r"(r[1]), "=r"(r[2]), "=r"(r[3]) : "r"(a));
}

// fp32-accumulate HMMA (hi pass)
__device__ __forceinline__ void mma_f32(float* c, const uint32_t* a, const uint32_t* b) {
    asm volatile(
        "mma.sync.aligned.m16n8k16.row.col.f32.f16.f16.f32 "
        "{%0,%1,%2,%3}, {%4,%5,%6,%7}, {%8,%9}, {%0,%1,%2,%3};"
        : "+f"(c[0]), "+f"(c[1]), "+f"(c[2]), "+f"(c[3])
        : "r"(a[0]), "r"(a[1]), "r"(a[2]), "r"(a[3]), "r"(b[0]), "r"(b[1]));
}
// fp16-accumulate HMMA (lo passes) — c[0]={(r,c0),(r,c1)}, c[1]={(r+8,c0),(r+8,c1)}
__device__ __forceinline__ void mma_f16(uint32_t* c, const uint32_t* a, const uint32_t* b) {
    asm volatile(
        "mma.sync.aligned.m16n8k16.row.col.f16.f16.f16.f16 "
        "{%0,%1}, {%2,%3,%4,%5}, {%6,%7}, {%0,%1};"
        : "+r"(c[0]), "+r"(c[1])
        : "r"(a[0]), "r"(a[1]), "r"(a[2]), "r"(a[3]), "r"(b[0]), "r"(b[1]));
}

__device__ __forceinline__ uint32_t hpack(float a, float b) {
    __half2 h = __floats2half2_rn(a, b);
    return *reinterpret_cast<uint32_t*>(&h);
}
__device__ __forceinline__ float2 hunpack(uint32_t u) {
    __half2 h = *reinterpret_cast<__half2*>(&u);
    return __half22float2(h);
}

// ---------------------------------------------------------------------------
// Split fp32 -> fp16 hi/lo
// ---------------------------------------------------------------------------
__global__ __launch_bounds__(256)
void split_f32(const float* __restrict__ in,
               __half* __restrict__ hi, __half* __restrict__ lo)
{
    const int i = blockIdx.x * 256 + threadIdx.x;
    float4 v = ((const float4*)in)[i];
    uint32_t h01 = hpack(v.x, v.y), h23 = hpack(v.z, v.w);
    float2 f01 = hunpack(h01), f23 = hunpack(h23);
    uint32_t l01 = hpack(v.x - f01.x, v.y - f01.y);
    uint32_t l23 = hpack(v.z - f23.x, v.w - f23.y);
    ((uint32_t*)hi)[2*i]   = h01;  ((uint32_t*)hi)[2*i+1] = h23;
    ((uint32_t*)lo)[2*i]   = l01;  ((uint32_t*)lo)[2*i+1] = l23;
}

// All 4 weights: W[K,N] fp32 -> W^T[N,K] fp16 hi/lo
__global__ __launch_bounds__(256)
void split_transpose_all(const float* __restrict__ W0, const float* __restrict__ W1,
                         const float* __restrict__ W2, const float* __restrict__ W3,
                         __half* __restrict__ hiT, __half* __restrict__ loT)
{
    __shared__ float t[32][33];
    const int w = blockIdx.z;
    const float* W = (w == 0) ? W0 : (w == 1) ? W1 : (w == 2) ? W2 : W3;
    __half* ho = hiT + (size_t)w * DD * DD;
    __half* lo = loT + (size_t)w * DD * DD;
    const int tx = threadIdx.x, ty = threadIdx.y;   // 32 x 8
    const int n0 = blockIdx.x * 32, k0 = blockIdx.y * 32;
#pragma unroll
    for (int r = ty; r < 32; r += 8)
        t[r][tx] = W[(size_t)(k0 + r) * GN + n0 + tx];
    __syncthreads();
#pragma unroll
    for (int r = ty; r < 32; r += 8) {
        const float v = t[tx][r];
        const __half hv = __float2half_rn(v);
        const __half lv = __float2half_rn(v - __half2float(hv));
        ho[(size_t)(n0 + r) * GK + k0 + tx] = hv;
        lo[(size_t)(n0 + r) * GK + k0 + tx] = lv;
    }
}

// ---------------------------------------------------------------------------
// GEMM core: hi pass (f32 acc) + two lo passes (f16 acc, folded per chunk).
// CTA 128x64, K-chunks of 64, double buffer, 8 warps as 4M x 2N.
// ---------------------------------------------------------------------------
#define G_AH 0
#define G_AL 16384
#define G_BH 32768
#define G_BL 40960
#define G_STAGE 49152
#define G_SMEM (2*G_STAGE)   // 96KB -> 2 CTAs/SM

struct GemmCtx {
    uint32_t sb;
    int arow, acc0, brow, bcc0;
    const __half *gAh, *gAl, *gBh, *gBl;
};

__device__ __forceinline__ void gemm_issue(const GemmCtx& g, int stage) {
    const uint32_t buf = g.sb + (stage & 1) * G_STAGE;
    const int ko = stage * 64;
#pragma unroll
    for (int i = 0; i < 4; ++i) {
        cp_async16(buf + G_AH + swz(g.arow, g.acc0 + i), g.gAh + ko + i * 8);
        cp_async16(buf + G_AL + swz(g.arow, g.acc0 + i), g.gAl + ko + i * 8);
    }
#pragma unroll
    for (int i = 0; i < 2; ++i) {
        cp_async16(buf + G_BH + swz(g.brow, g.bcc0 + i), g.gBh + ko + i * 8);
        cp_async16(buf + G_BL + swz(g.brow, g.bcc0 + i), g.gBl + ko + i * 8);
    }
    CP_COMMIT();
}

__device__ __forceinline__ void gemm_mainloop(const GemmCtx& g, int lane,
                                              int wm, int wn, float c[2][4][4]) {
    gemm_issue(g, 0);
    for (int s = 0; s < 16; ++s) {
        if (s + 1 < 16) { gemm_issue(g, s + 1); CP_WAIT1(); } else { CP_WAIT0(); }
        __syncthreads();
        const uint32_t base = g.sb + (s & 1) * G_STAGE;
        uint32_t cl[2][4][2];
#pragma unroll
        for (int a = 0; a < 2; ++a)
#pragma unroll
            for (int b = 0; b < 4; ++b) { cl[a][b][0] = 0u; cl[a][b][1] = 0u; }
#pragma unroll
        for (int kt = 0; kt < 4; ++kt) {
            uint32_t a0h[4], a1h[4], a0l[4], a1l[4];
            const uint32_t ar = wm * 32 + (lane & 15);
            const uint32_t ac = kt * 2 + (lane >> 4);
            ldsm_x4(a0h, base + G_AH + swz(ar, ac));
            ldsm_x4(a1h, base + G_AH + swz(ar + 16, ac));
            ldsm_x4(a0l, base + G_AL + swz(ar, ac));
            ldsm_x4(a1l, base + G_AL + swz(ar + 16, ac));
#pragma unroll
            for (int np = 0; np < 2; ++np) {
                uint32_t bh[4], bl[4];
                const uint32_t br  = wn * 32 + (2 * np + (lane >> 4)) * 8 + (lane & 7);
                const uint32_t bcc = kt * 2 + ((lane >> 3) & 1);
                ldsm_x4(bh, base + G_BH + swz(br, bcc));
                ldsm_x4(bl, base + G_BL + swz(br, bcc));
                // hi pass: Ah*Bh (f32 acc)
                mma_f32(c[0][2*np],   a0h, bh); mma_f32(c[0][2*np+1], a0h, bh + 2);
                mma_f32(c[1][2*np],   a1h, bh); mma_f32(c[1][2*np+1], a1h, bh + 2);
                // lo passes: Ah*Bl + Al*Bh (f16 acc)
                mma_f16(cl[0][2*np],   a0h, bl); mma_f16(cl[0][2*np+1], a0h, bl + 2);
                mma_f16(cl[1][2*np],   a1h, bl); mma_f16(cl[1][2*np+1], a1h, bl + 2);
                mma_f16(cl[0][2*np],   a0l, bh); mma_f16(cl[0][2*np+1], a0l, bh + 2);
                mma_f16(cl[1][2*np],   a1l, bh); mma_f16(cl[1][2*np+1], a1l, bh + 2);
            }
        }
        // fold f16 lo accumulators into f32
#pragma unroll
        for (int a = 0; a < 2; ++a)
#pragma unroll
            for (int b = 0; b < 4; ++b) {
                const float2 l0 = hunpack(cl[a][b][0]);
                const float2 l1 = hunpack(cl[a][b][1]);
                c[a][b][0] += l0.x; c[a][b][1] += l0.y;
                c[a][b][2] += l1.x; c[a][b][3] += l1.y;
            }
        __syncthreads();
    }
}

// Fused QKV projection: grid (16, 32, 3)
__global__ __launch_bounds__(256, 2)
void gemm_qkv(const __half* __restrict__ Ahi, const __half* __restrict__ Alo,
              const __half* __restrict__ Whi, const __half* __restrict__ Wlo,
              const float* __restrict__ bq, const float* __restrict__ bk,
              const float* __restrict__ bv,
              __half* __restrict__ qhi, __half* __restrict__ qlo,
              __half* __restrict__ khi, __half* __restrict__ klo,
              __half* __restrict__ vhi, __half* __restrict__ vlo)
{
    extern __shared__ char smraw[];
    const int tid = threadIdx.x, lane = tid & 31, warp = tid >> 5;
    const int wm = warp >> 1, wn = warp & 1;
    const int m0 = blockIdx.y * 128, n0 = blockIdx.x * 64;
    const int z = blockIdx.z;

    const float* bias = (z == 0) ? bq : (z == 1) ? bk : bv;
    __half* Chi = (z == 0) ? qhi : (z == 1) ? khi : vhi;
    __half* Clo = (z == 0) ? qlo : (z == 1) ? klo : vlo;
    const float scale = (z == 0) ? 0.125f : 1.0f;
    const __half* Bhi = Whi + (size_t)z * DD * DD;
    const __half* Blo = Wlo + (size_t)z * DD * DD;

    GemmCtx g;
    g.sb = smem_u32(smraw);
    g.arow = tid >> 1;  g.acc0 = (tid & 1) * 4;
    g.brow = tid >> 2;  g.bcc0 = (tid & 3) * 2;
    g.gAh = Ahi + (size_t)(m0 + g.arow) * GK + g.acc0 * 8;
    g.gAl = Alo + (size_t)(m0 + g.arow) * GK + g.acc0 * 8;
    g.gBh = Bhi + (size_t)(n0 + g.brow) * GK + g.bcc0 * 8;
    g.gBl = Blo + (size_t)(n0 + g.brow) * GK + g.bcc0 * 8;

    float c[2][4][4];
#pragma unroll
    for (int a = 0; a < 2; ++a)
#pragma unroll
        for (int b = 0; b < 4; ++b)
#pragma unroll
            for (int e = 0; e < 4; ++e) c[a][b][e] = 0.f;

    gemm_mainloop(g, lane, wm, wn, c);

#pragma unroll
    for (int mt = 0; mt < 2; ++mt) {
#pragma unroll
        for (int nt = 0; nt < 4; ++nt) {
            const int col = n0 + wn * 32 + nt * 8 + (lane & 3) * 2;
            const float2 bs = *(const float2*)(bias + col);
#pragma unroll
            for (int hf = 0; hf < 2; ++hf) {
                const int row = m0 + wm * 32 + mt * 16 + (lane >> 2) + hf * 8;
                float v0 = (c[mt][nt][hf*2]     + bs.x) * scale;
                float v1 = (c[mt][nt][hf*2 + 1] + bs.y) * scale;
                const uint32_t hp = hpack(v0, v1);
                const float2 hfv = hunpack(hp);
                const uint32_t lp = hpack(v0 - hfv.x, v1 - hfv.y);
                const int bb = row >> 11, sq = row & 2047;
                const int hh = col >> 6,  hd = col & 63;
                const size_t off = (((size_t)(bb * HH + hh)) * SS + sq) * HD + hd;
                *(uint32_t*)(Chi + off) = hp;
                *(uint32_t*)(Clo + off) = lp;
            }
        }
    }
}

// Output projection: fp32 C + bias
__global__ __launch_bounds__(256, 2)
void gemm_out(const __half* __restrict__ Ahi, const __half* __restrict__ Alo,
              const __half* __restrict__ Bhi, const __half* __restrict__ Blo,
              const float* __restrict__ bias, float* __restrict__ C)
{
    extern __shared__ char smraw[];
    const int tid = threadIdx.x, lane = tid & 31, warp = tid >> 5;
    const int wm = warp >> 1, wn = warp & 1;
    const int m0 = blockIdx.y * 128, n0 = blockIdx.x * 64;

    GemmCtx g;
    g.sb = smem_u32(smraw);
    g.arow = tid >> 1;  g.acc0 = (tid & 1) * 4;
    g.brow = tid >> 2;  g.bcc0 = (tid & 3) * 2;
    g.gAh = Ahi + (size_t)(m0 + g.arow) * GK + g.acc0 * 8;
    g.gAl = Alo + (size_t)(m0 + g.arow) * GK + g.acc0 * 8;
    g.gBh = Bhi + (size_t)(n0 + g.brow) * GK + g.bcc0 * 8;
    g.gBl = Blo + (size_t)(n0 + g.brow) * GK + g.bcc0 * 8;

    float c[2][4][4];
#pragma unroll
    for (int a = 0; a < 2; ++a)
#pragma unroll
        for (int b = 0; b < 4; ++b)
#pragma unroll
            for (int e = 0; e < 4; ++e) c[a][b][e] = 0.f;

    gemm_mainloop(g, lane, wm, wn, c);

#pragma unroll
    for (int mt = 0; mt < 2; ++mt) {
#pragma unroll
        for (int nt = 0; nt < 4; ++nt) {
            const int col = n0 + wn * 32 + nt * 8 + (lane & 3) * 2;
            const float2 bs = *(const float2*)(bias + col);
#pragma unroll
            for (int hf = 0; hf < 2; ++hf) {
                const int row = m0 + wm * 32 + mt * 16 + (lane >> 2) + hf * 8;
                const float v0 = c[mt][nt][hf*2]     + bs.x;
                const float v1 = c[mt][nt][hf*2 + 1] + bs.y;
                *(float2*)(C + (size_t)row * GN + col) = make_float2(v0, v1);
            }
        }
    }
}

// ---------------------------------------------------------------------------
// Flash attention: hi passes f32-acc, lo passes f16-acc folded per tile.
// CTA: 128 Q rows, 64-key tiles, 8 warps. P-lo streams via smem (Q-lo region).
// ---------------------------------------------------------------------------
#define F_QHI 0
#define F_QLO 16384          // after s==0 reads, reused as P-lo tile
#define F_ST0 32768
#define F_STSZ 32768
#define F_KHI 0
#define F_KLO 8192
#define F_VHI 16384
#define F_VLO 24576
#define F_EMI (F_ST0 + 2*F_STSZ)
#define F_CMI (F_EMI + 512)
#define F_SMEM (F_CMI + 512)

__global__ __launch_bounds__(256, 2)
void flash_mma(const int* __restrict__ cause, const int* __restrict__ effect,
               const float* __restrict__ strength)
{
    extern __shared__ char smraw[];
    const uint32_t sb = smem_u32(smraw);
    const int tid = threadIdx.x, lane = tid & 31, warp = tid >> 5;
    const int b = blockIdx.z, h = blockIdx.y, q0 = blockIdx.x * 128;
    const float fm1 = 1.0f - 0.5f * strength[0];

    const size_t headoff = ((size_t)(b * HH + h)) * SS;

    {   // prologue: Q hi/lo + cause mask (joins stage-0 commit group)
        const __half* qs[2] = { g_qhi + (headoff + q0) * HD,
                                g_qlo + (headoff + q0) * HD };
        const int r = tid >> 1, c0 = (tid & 1) * 4;
#pragma unroll
        for (int t = 0; t < 2; ++t)
#pragma unroll
            for (int i = 0; i < 4; ++i)
                cp_async16(sb + t * 16384 + swz(r, c0 + i),
                           qs[t] + (size_t)r * HD + (c0 + i) * 8);
        if (tid < 128) cp_async4(sb + F_CMI + tid * 4, cause + b * SS + q0 + tid);
    }

    auto issue = [&](int s) {
        const uint32_t st = sb + F_ST0 + (s & 1) * F_STSZ;
        const int kt0 = s * 64;
        const __half* srcs[4] = { g_khi + (headoff + kt0) * HD,
                                  g_klo + (headoff + kt0) * HD,
                                  g_vhi + (headoff + kt0) * HD,
                                  g_vlo + (headoff + kt0) * HD };
        const int r = tid >> 2, cc0 = (tid & 3) * 2;
#pragma unroll
        for (int t = 0; t < 4; ++t)
#pragma unroll
            for (int i = 0; i < 2; ++i)
                cp_async16(st + t * 8192 + swz(r, cc0 + i),
                           srcs[t] + (size_t)r * HD + (cc0 + i) * 8);
        if (tid < 64) cp_async4(sb + F_EMI + (s & 1) * 256 + tid * 4,
                                effect + b * SS + kt0 + tid);
        CP_COMMIT();
    };

    issue(0);

    float o[8][4];
#pragma unroll
    for (int i = 0; i < 8; ++i)
#pragma unroll
        for (int e = 0; e < 4; ++e) o[i][e] = 0.f;
    float mrow0 = -1e30f, mrow1 = -1e30f, lrow0 = 0.f, lrow1 = 0.f;
    uint32_t qh[4][4], ql[4][4];
    int cm0 = 0, cm1 = 0;

    const uint32_t prw0 = warp * 16 + (lane >> 2);
    const uint32_t plo  = sb + F_QLO;

    for (int s = 0; s < 32; ++s) {
        if (s + 1 < 32) { issue(s + 1); CP_WAIT1(); } else { CP_WAIT0(); }
        __syncthreads();

        if (s == 0) {
            const uint32_t ar = warp * 16 + (lane & 15);
#pragma unroll
            for (int kt = 0; kt < 4; ++kt) {
                const uint32_t cc = kt * 2 + (lane >> 4);
                ldsm_x4(qh[kt], sb + F_QHI + swz(ar, cc));
                ldsm_x4(ql[kt], sb + F_QLO + swz(ar, cc));
            }
            const int* cmi = (const int*)(smraw + F_CMI);
            cm0 = cmi[warp * 16 + (lane >> 2)];
            cm1 = cmi[warp * 16 + (lane >> 2) + 8];
        }

        const uint32_t st = sb + F_ST0 + (s & 1) * F_STSZ;

        // ---- S = Q K^T : hi pass f32-acc, lo passes f16-acc
        float sc[8][4];
        uint32_t scl[8][2];
#pragma unroll
        for (int i = 0; i < 8; ++i) {
            sc[i][0] = sc[i][1] = sc[i][2] = sc[i][3] = 0.f;
            scl[i][0] = scl[i][1] = 0u;
        }
#pragma unroll
        for (int kt = 0; kt < 4; ++kt) {
#pragma unroll
            for (int np = 0; np < 4; ++np) {
                uint32_t kh[4], kl[4];
                const uint32_t br  = (2 * np + (lane >> 4)) * 8 + (lane & 7);
                const uint32_t bcc = kt * 2 + ((lane >> 3) & 1);
                ldsm_x4(kh, st + F_KHI + swz(br, bcc));
                ldsm_x4(kl, st + F_KLO + swz(br, bcc));
                mma_f32(sc[2*np],    qh[kt], kh); mma_f32(sc[2*np+1],  qh[kt], kh + 2);
                mma_f16(scl[2*np],   qh[kt], kl); mma_f16(scl[2*np+1], qh[kt], kl + 2);
                mma_f16(scl[2*np],   ql[kt], kh); mma_f16(scl[2*np+1], ql[kt], kh + 2);
            }
        }
#pragma unroll
        for (int i = 0; i < 8; ++i) {
            const float2 l0 = hunpack(scl[i][0]);
            const float2 l1 = hunpack(scl[i][1]);
            sc[i][0] += l0.x; sc[i][1] += l0.y;
            sc[i][2] += l1.x; sc[i][3] += l1.y;
        }

        // ---- mask + online softmax; P-hi regs, P-lo -> smem
        const int* emi = (const int*)(smraw + F_EMI + (s & 1) * 256);
        float tm0 = -1e30f, tm1 = -1e30f;
#pragma unroll
        for (int nt = 0; nt < 8; ++nt) {
            const int col = nt * 8 + (lane & 3) * 2;
            const int e0 = emi[col], e1 = emi[col + 1];
            sc[nt][0] *= (cm0 && e0) ? fm1 : 1.0f;
            sc[nt][1] *= (cm0 && e1) ? fm1 : 1.0f;
            sc[nt][2] *= (cm1 && e0) ? fm1 : 1.0f;
            sc[nt][3] *= (cm1 && e1) ? fm1 : 1.0f;
            tm0 = fmaxf(tm0, fmaxf(sc[nt][0], sc[nt][1]));
            tm1 = fmaxf(tm1, fmaxf(sc[nt][2], sc[nt][3]));
        }
        tm0 = fmaxf(tm0, __shfl_xor_sync(0xffffffffu, tm0, 1));
        tm0 = fmaxf(tm0, __shfl_xor_sync(0xffffffffu, tm0, 2));
        tm1 = fmaxf(tm1, __shfl_xor_sync(0xffffffffu, tm1, 1));
        tm1 = fmaxf(tm1, __shfl_xor_sync(0xffffffffu, tm1, 2));
        const float mn0 = fmaxf(mrow0, tm0), mn1 = fmaxf(mrow1, tm1);
        const float al0 = __expf(mrow0 - mn0), al1 = __expf(mrow1 - mn1);
        mrow0 = mn0; mrow1 = mn1;

        float sum0 = 0.f, sum1 = 0.f;
        uint32_t pha[8], phb[8];
#pragma unroll
        for (int nt = 0; nt < 8; ++nt) {
            const float p0 = __expf(sc[nt][0] - mn0);
            const float p1 = __expf(sc[nt][1] - mn0);
            const float p2 = __expf(sc[nt][2] - mn1);
            const float p3 = __expf(sc[nt][3] - mn1);
            sum0 += p0 + p1; sum1 += p2 + p3;
            pha[nt] = hpack(p0, p1);
            phb[nt] = hpack(p2, p3);
            const float2 fa = hunpack(pha[nt]);
            const float2 fb = hunpack(phb[nt]);
            const uint32_t la = hpack(p0 - fa.x, p1 - fa.y);
            const uint32_t lb = hpack(p2 - fb.x, p3 - fb.y);
            const uint32_t off = ((uint32_t)nt ^ (prw0 & 7u)) * 16u + (lane & 3) * 4;
            *(uint32_t*)(smraw + F_QLO + prw0 * 128 + off) = la;
            const uint32_t off2 = ((uint32_t)nt ^ ((prw0 + 8) & 7u)) * 16u + (lane & 3) * 4;
            *(uint32_t*)(smraw + F_QLO + (prw0 + 8) * 128 + off2) = lb;
        }
        sum0 += __shfl_xor_sync(0xffffffffu, sum0, 1);
        sum0 += __shfl_xor_sync(0xffffffffu, sum0, 2);
        sum1 += __shfl_xor_sync(0xffffffffu, sum1, 1);
        sum1 += __shfl_xor_sync(0xffffffffu, sum1, 2);
        lrow0 = lrow0 * al0 + sum0;
        lrow1 = lrow1 * al1 + sum1;
#pragma unroll
        for (int nt = 0; nt < 8; ++nt) {
            o[nt][0] *= al0; o[nt][1] *= al0;
            o[nt][2] *= al1; o[nt][3] *= al1;
        }

        // ---- O += P V : hi f32-acc into o, lo f16-acc into ol, fold after
        uint32_t ol[8][2];
#pragma unroll
        for (int i = 0; i < 8; ++i) { ol[i][0] = 0u; ol[i][1] = 0u; }
        __syncwarp();   // P-lo STS visible to ldmatrix (same warp, cross-lane)
#pragma unroll
        for (int kt = 0; kt < 4; ++kt) {
            uint32_t ph[4] = { pha[2*kt], phb[2*kt], pha[2*kt+1], phb[2*kt+1] };
            uint32_t pl[4];
            const uint32_t ar = warp * 16 + (lane & 15);
            ldsm_x4(pl, plo + swz(ar, kt * 2 + (lane >> 4)));
#pragma unroll
            for (int np = 0; np < 4; ++np) {
                uint32_t vh[4], vl[4];
                const uint32_t vr  = kt * 16 + (((lane >> 3) & 1) << 3) + (lane & 7);
                const uint32_t vcc = 2 * np + (lane >> 4);
                ldsm_x4_t(vh, st + F_VHI + swz(vr, vcc));
                ldsm_x4_t(vl, st + F_VLO + swz(vr, vcc));
                mma_f32(o[2*np],    ph, vh); mma_f32(o[2*np+1],  ph, vh + 2);
                mma_f16(ol[2*np],   ph, vl); mma_f16(ol[2*np+1], ph, vl + 2);
                mma_f16(ol[2*np],   pl, vh); mma_f16(ol[2*np+1], pl, vh + 2);
            }
        }
#pragma unroll
        for (int i = 0; i < 8; ++i) {
            const float2 l0 = hunpack(ol[i][0]);
            const float2 l1 = hunpack(ol[i][1]);
            o[i][0] += l0.x; o[i][1] += l0.y;
            o[i][2] += l1.x; o[i][3] += l1.y;
        }
        __syncthreads();
    }

    // ---- epilogue
    const float inv0 = 1.0f / lrow0, inv1 = 1.0f / lrow1;
    const int row0 = b * SS + q0 + warp * 16 + (lane >> 2);
#pragma unroll
    for (int nt = 0; nt < 8; ++nt) {
        const int col = h * 64 + nt * 8 + (lane & 3) * 2;
        const float v0 = o[nt][0] * inv0, v1 = o[nt][1] * inv0;
        const float v2 = o[nt][2] * inv1, v3 = o[nt][3] * inv1;
        const uint32_t h0 = hpack(v0, v1);
        const float2 f0 = hunpack(h0);
        const uint32_t l0 = hpack(v0 - f0.x, v1 - f0.y);
        const uint32_t h1 = hpack(v2, v3);
        const float2 f1 = hunpack(h1);
        const uint32_t l1 = hpack(v2 - f1.x, v3 - f1.y);
        *(uint32_t*)(g_ohi + (size_t)row0 * DD + col)       = h0;
        *(uint32_t*)(g_olo + (size_t)row0 * DD + col)       = l0;
        *(uint32_t*)(g_ohi + (size_t)(row0 + 8) * DD + col) = h1;
        *(uint32_t*)(g_olo + (size_t)(row0 + 8) * DD + col) = l1;
    }
}

// ---------------------------------------------------------------------------
extern "C" void kernel_launch(void* const* d_in, const int* in_sizes, int n_in,
                              void* d_out, int out_size)
{
    const float* x        = (const float*)d_in[0];
    const int*   cause    = (const int*)d_in[1];
    const int*   effect   = (const int*)d_in[2];
    const float* strength = (const float*)d_in[3];
    const float* Wq = (const float*)d_in[4];
    const float* bq = (const float*)d_in[5];
    const float* Wk = (const float*)d_in[6];
    const float* bk = (const float*)d_in[7];
    const float* Wv = (const float*)d_in[8];
    const float* bv = (const float*)d_in[9];
    const float* Wo = (const float*)d_in[10];
    const float* bo = (const float*)d_in[11];
    float* out = (float*)d_out;

    void *pxhi, *pxlo, *pwhi, *pwlo;
    void *pqhi, *pqlo, *pkhi, *pklo, *pvhi, *pvlo, *pohi, *polo;
    cudaGetSymbolAddress(&pxhi, g_xhi);  cudaGetSymbolAddress(&pxlo, g_xlo);
    cudaGetSymbolAddress(&pwhi, g_wThi); cudaGetSymbolAddress(&pwlo, g_wTlo);
    cudaGetSymbolAddress(&pqhi, g_qhi);  cudaGetSymbolAddress(&pqlo, g_qlo);
    cudaGetSymbolAddress(&pkhi, g_khi);  cudaGetSymbolAddress(&pklo, g_klo);
    cudaGetSymbolAddress(&pvhi, g_vhi);  cudaGetSymbolAddress(&pvlo, g_vlo);
    cudaGetSymbolAddress(&pohi, g_ohi);  cudaGetSymbolAddress(&polo, g_olo);

    __half* xhi = (__half*)pxhi; __half* xlo = (__half*)pxlo;
    __half* whi = (__half*)pwhi; __half* wlo = (__half*)pwlo;

    static bool attr_set = false;
    if (!attr_set) {
        cudaFuncSetAttribute(gemm_qkv,  cudaFuncAttributeMaxDynamicSharedMemorySize, G_SMEM);
        cudaFuncSetAttribute(gemm_out,  cudaFuncAttributeMaxDynamicSharedMemorySize, G_SMEM);
        cudaFuncSetAttribute(flash_mma, cudaFuncAttributeMaxDynamicSharedMemorySize, F_SMEM);
        attr_set = true;
    }

    split_f32<<<GM * DD / 4 / 256, 256>>>(x, xhi, xlo);
    dim3 tgrid(32, 32, 4), tblk(32, 8);
    split_transpose_all<<<tgrid, tblk>>>(Wq, Wk, Wv, Wo, whi, wlo);

    dim3 qgrid(GN / 64, GM / 128, 3);   // (16, 32, 3)
    gemm_qkv<<<qgrid, 256, G_SMEM>>>(xhi, xlo, whi, wlo, bq, bk, bv,
                                     (__half*)pqhi, (__half*)pqlo,
                                     (__half*)pkhi, (__half*)pklo,
                                     (__half*)pvhi, (__half*)pvlo);

    dim3 fgrid(SS / 128, HH, BB);       // (16, 16, 2)
    flash_mma<<<fgrid, 256, F_SMEM>>>(cause, effect, strength);

    dim3 ogrid(GN / 64, GM / 128);      // (16, 32)
    gemm_out<<<ogrid, 256, G_SMEM>>>((__half*)pohi, (__half*)polo,
                                     whi + 3*(size_t)DD*DD, wlo + 3*(size_t)DD*DD,
                                     bo, out);
}